// round 1
// baseline (speedup 1.0000x reference)
#include <cuda_runtime.h>
#include <math.h>

// Problem constants
static constexpr int D    = 768;
static constexpr int H    = 12;
static constexpr int HD   = 64;
static constexpr int DFF  = 3072;
static constexpr int B    = 2;
static constexpr int S    = 4096;
static constexpr int NTOK = B * S;   // 8192

// ---------------- scratch (static device globals; no allocation) ------------
__device__ float g_h  [NTOK * D];    // LN1 output
__device__ float g_q  [NTOK * D];
__device__ float g_k  [NTOK * D];
__device__ float g_v  [NTOK * D];
__device__ float g_ctx[NTOK * D];    // attention context
__device__ float g_x1 [NTOK * D];    // x + self-attn
__device__ float g_h2 [NTOK * D];    // LN2 output
__device__ float g_ff [NTOK * DFF];  // relu(h2@W1+b1)

// ---------------- LayerNorm: one block per row, 256 threads -----------------
__global__ __launch_bounds__(256) void ln_kernel(
    const float* __restrict__ x,
    const float* __restrict__ gamma,
    const float* __restrict__ beta,
    float* __restrict__ out)
{
    int row = blockIdx.x;
    int tid = threadIdx.x;
    const float* xr = x + (size_t)row * D;

    float v0 = xr[tid];
    float v1 = xr[tid + 256];
    float v2 = xr[tid + 512];
    float s  = v0 + v1 + v2;
    float ss = v0*v0 + v1*v1 + v2*v2;

    #pragma unroll
    for (int off = 16; off; off >>= 1) {
        s  += __shfl_down_sync(0xffffffffu, s,  off);
        ss += __shfl_down_sync(0xffffffffu, ss, off);
    }

    __shared__ float rs[8], rss[8];
    __shared__ float mu_s, rstd_s;
    if ((tid & 31) == 0) { rs[tid >> 5] = s; rss[tid >> 5] = ss; }
    __syncthreads();
    if (tid == 0) {
        float S_ = 0.f, SS_ = 0.f;
        #pragma unroll
        for (int w = 0; w < 8; w++) { S_ += rs[w]; SS_ += rss[w]; }
        float mu  = S_ * (1.0f / (float)D);
        float var = SS_ * (1.0f / (float)D) - mu * mu;
        mu_s   = mu;
        rstd_s = rsqrtf(var + 1e-5f);
    }
    __syncthreads();
    float mu = mu_s, r = rstd_s;

    float* orow = out + (size_t)row * D;
    orow[tid]       = (v0 - mu) * r * gamma[tid]       + beta[tid];
    orow[tid + 256] = (v1 - mu) * r * gamma[tid + 256] + beta[tid + 256];
    orow[tid + 512] = (v2 - mu) * r * gamma[tid + 512] + beta[tid + 512];
}

// ---------------- SGEMM: C = A[M,K] @ Bw[K,N] + bias (+relu | +residual) ----
// 128x128 tile, BK=8, 8x8 microtile, 256 threads.
// EPI: 0 = bias, 1 = bias+relu, 2 = bias+residual
template <int EPI>
__global__ __launch_bounds__(256) void sgemm_kernel(
    int M, int N, int K,
    const float* __restrict__ A,
    const float* __restrict__ Bw,
    const float* __restrict__ bias,
    const float* __restrict__ res,
    float* __restrict__ C)
{
    __shared__ __align__(16) float As[8][128];  // transposed: As[k][m]
    __shared__ __align__(16) float Bs[8][128];  // Bs[k][n]

    int bx = blockIdx.x;   // N tiles
    int by = blockIdx.y;   // M tiles
    int tid = threadIdx.x;
    int tr = tid >> 4;     // 0..15
    int tc = tid & 15;     // 0..15

    const float* Ab = A  + (size_t)by * 128 * K;
    const float* Bb = Bw + (size_t)bx * 128;

    int aRow = tid >> 1;          // 0..127
    int aCol = (tid & 1) * 4;     // 0 or 4
    int bRow = tid >> 5;          // 0..7
    int bCol = (tid & 31) * 4;    // 0..124

    float acc[8][8];
    #pragma unroll
    for (int i = 0; i < 8; i++)
        #pragma unroll
        for (int j = 0; j < 8; j++) acc[i][j] = 0.f;

    for (int k0 = 0; k0 < K; k0 += 8) {
        float4 av = *(const float4*)(Ab + (size_t)aRow * K + k0 + aCol);
        As[aCol + 0][aRow] = av.x;
        As[aCol + 1][aRow] = av.y;
        As[aCol + 2][aRow] = av.z;
        As[aCol + 3][aRow] = av.w;
        float4 bv = *(const float4*)(Bb + (size_t)(k0 + bRow) * N + bCol);
        *(float4*)&Bs[bRow][bCol] = bv;
        __syncthreads();

        #pragma unroll
        for (int k = 0; k < 8; k++) {
            float4 a0 = *(const float4*)&As[k][tr * 8];
            float4 a1 = *(const float4*)&As[k][tr * 8 + 4];
            float4 b0 = *(const float4*)&Bs[k][tc * 8];
            float4 b1 = *(const float4*)&Bs[k][tc * 8 + 4];
            float rm[8] = {a0.x, a0.y, a0.z, a0.w, a1.x, a1.y, a1.z, a1.w};
            float rn[8] = {b0.x, b0.y, b0.z, b0.w, b1.x, b1.y, b1.z, b1.w};
            #pragma unroll
            for (int i = 0; i < 8; i++)
                #pragma unroll
                for (int j = 0; j < 8; j++)
                    acc[i][j] += rm[i] * rn[j];
        }
        __syncthreads();
    }

    int row0 = by * 128 + tr * 8;
    int col0 = bx * 128 + tc * 8;
    float barr[8];
    #pragma unroll
    for (int j = 0; j < 8; j++) barr[j] = bias[col0 + j];

    #pragma unroll
    for (int i = 0; i < 8; i++) {
        float* crow = C + (size_t)(row0 + i) * N + col0;
        float vj[8];
        #pragma unroll
        for (int j = 0; j < 8; j++) {
            float v = acc[i][j] + barr[j];
            if (EPI == 1) v = fmaxf(v, 0.f);
            vj[j] = v;
        }
        if (EPI == 2) {
            const float* rrow = res + (size_t)(row0 + i) * N + col0;
            #pragma unroll
            for (int j = 0; j < 8; j++) vj[j] += rrow[j];
        }
        *(float4*)(crow)     = make_float4(vj[0], vj[1], vj[2], vj[3]);
        *(float4*)(crow + 4) = make_float4(vj[4], vj[5], vj[6], vj[7]);
    }
}

// ---------------- Flash attention (causal + key mask) -----------------------
// grid = (S/64, H, B), block = 256 threads.
// 64 query rows per block; each row handled by 4 lanes; each lane owns 16 of
// the 64 head dims for Q (registers) and the output accumulator.
__global__ __launch_bounds__(256, 1) void flash_kernel(
    const float* __restrict__ Q,
    const float* __restrict__ Kp,
    const float* __restrict__ Vp,
    const int*   __restrict__ am,
    float* __restrict__ O)
{
    __shared__ __align__(16) float Ks[64][HD + 4];
    __shared__ __align__(16) float Vs[64][HD + 4];
    __shared__ int ms[64];

    int qb = blockIdx.x;
    int h  = blockIdx.y;
    int b  = blockIdx.z;
    int tid  = threadIdx.x;
    int lane = tid & 31;
    int warp = tid >> 5;

    int rowl  = warp * 8 + (lane >> 2);  // 0..63 local query row
    int qpart = lane & 3;                // 0..3  (dim / k-split partition)
    int qg    = qb * 64 + rowl;          // global query index

    const float scale = 0.125f;          // 1/sqrt(64)

    // Q slice in registers, pre-scaled
    float qreg[16];
    {
        const float* qptr = Q + ((size_t)b * S + qg) * D + h * HD + qpart * 16;
        #pragma unroll
        for (int i = 0; i < 16; i += 4) {
            float4 v = *(const float4*)(qptr + i);
            qreg[i + 0] = v.x * scale;
            qreg[i + 1] = v.y * scale;
            qreg[i + 2] = v.z * scale;
            qreg[i + 3] = v.w * scale;
        }
    }

    float m = -INFINITY, l = 0.f;
    float acc[16];
    #pragma unroll
    for (int i = 0; i < 16; i++) acc[i] = 0.f;

    int nkv = qb + 1;  // causal: key blocks 0..qb
    for (int kv = 0; kv < nkv; kv++) {
        // cooperative K/V tile load
        {
            int r = tid >> 2;
            int c = (tid & 3) * 16;
            const float* kp = Kp + ((size_t)b * S + kv * 64 + r) * D + h * HD + c;
            const float* vp = Vp + ((size_t)b * S + kv * 64 + r) * D + h * HD + c;
            #pragma unroll
            for (int i = 0; i < 16; i += 4) {
                *(float4*)&Ks[r][c + i] = *(const float4*)(kp + i);
                *(float4*)&Vs[r][c + i] = *(const float4*)(vp + i);
            }
            if (tid < 64) ms[tid] = am[(size_t)b * S + kv * 64 + tid];
        }
        __syncthreads();

        // partial dot over this lane's 16 k-dims, all 64 key columns
        float s[64];
        #pragma unroll
        for (int j = 0; j < 64; j++) {
            float a = 0.f;
            #pragma unroll
            for (int kk = 0; kk < 16; kk++)
                a += qreg[kk] * Ks[j][qpart * 16 + kk];
            s[j] = a;
        }
        // butterfly-sum within the 4-lane group -> every lane has full scores
        #pragma unroll
        for (int j = 0; j < 64; j++) {
            s[j] += __shfl_xor_sync(0xffffffffu, s[j], 1);
            s[j] += __shfl_xor_sync(0xffffffffu, s[j], 2);
        }

        // mask + running max
        float mb = -INFINITY;
        #pragma unroll
        for (int j = 0; j < 64; j++) {
            int kg = kv * 64 + j;
            bool keep = (kg <= qg) && (ms[j] != 0);
            s[j] = keep ? s[j] : -INFINITY;
            mb = fmaxf(mb, s[j]);
        }

        float mnew = fmaxf(m, mb);
        float corr, psum = 0.f;
        if (mnew == -INFINITY) {
            corr = 1.f;
            #pragma unroll
            for (int j = 0; j < 64; j++) s[j] = 0.f;
        } else {
            corr = __expf(m - mnew);  // m == -inf -> 0
            #pragma unroll
            for (int j = 0; j < 64; j++) {
                s[j] = __expf(s[j] - mnew);  // -inf -> 0
                psum += s[j];
            }
        }
        m = mnew;
        l = l * corr + psum;

        #pragma unroll
        for (int dd = 0; dd < 16; dd++) acc[dd] *= corr;

        #pragma unroll
        for (int j = 0; j < 64; j++) {
            float pj = s[j];
            #pragma unroll
            for (int dd = 0; dd < 16; dd++)
                acc[dd] += pj * Vs[j][qpart * 16 + dd];
        }
        __syncthreads();
    }

    float inv = 1.0f / l;
    float* optr = O + ((size_t)b * S + qg) * D + h * HD + qpart * 16;
    #pragma unroll
    for (int dd = 0; dd < 16; dd += 4) {
        *(float4*)(optr + dd) = make_float4(acc[dd] * inv, acc[dd+1] * inv,
                                            acc[dd+2] * inv, acc[dd+3] * inv);
    }
}

// ---------------- launch ----------------------------------------------------
extern "C" void kernel_launch(void* const* d_in, const int* in_sizes, int n_in,
                              void* d_out, int out_size)
{
    const float* x    = (const float*)d_in[0];
    const int*   am   = (const int*)  d_in[1];
    const float* ln1g = (const float*)d_in[2];
    const float* ln1b = (const float*)d_in[3];
    const float* ln2g = (const float*)d_in[4];
    const float* ln2b = (const float*)d_in[5];
    const float* Wq   = (const float*)d_in[6];
    const float* bq   = (const float*)d_in[7];
    const float* Wk   = (const float*)d_in[8];
    const float* bk   = (const float*)d_in[9];
    const float* Wv   = (const float*)d_in[10];
    const float* bv   = (const float*)d_in[11];
    const float* Wo   = (const float*)d_in[12];
    const float* bo   = (const float*)d_in[13];
    const float* W1   = (const float*)d_in[14];
    const float* b1   = (const float*)d_in[15];
    const float* W2   = (const float*)d_in[16];
    const float* b2   = (const float*)d_in[17];
    float* out = (float*)d_out;

    float *h, *q, *k, *v, *ctx, *x1, *h2, *ff;
    cudaGetSymbolAddress((void**)&h,   g_h);
    cudaGetSymbolAddress((void**)&q,   g_q);
    cudaGetSymbolAddress((void**)&k,   g_k);
    cudaGetSymbolAddress((void**)&v,   g_v);
    cudaGetSymbolAddress((void**)&ctx, g_ctx);
    cudaGetSymbolAddress((void**)&x1,  g_x1);
    cudaGetSymbolAddress((void**)&h2,  g_h2);
    cudaGetSymbolAddress((void**)&ff,  g_ff);

    dim3 blk(256);
    dim3 gD(D / 128, NTOK / 128);      // N=768 GEMMs
    dim3 gF(DFF / 128, NTOK / 128);    // N=3072 GEMM

    // LN1
    ln_kernel<<<NTOK, blk>>>(x, ln1g, ln1b, h);
    // QKV projections
    sgemm_kernel<0><<<gD, blk>>>(NTOK, D, D, h, Wq, bq, nullptr, q);
    sgemm_kernel<0><<<gD, blk>>>(NTOK, D, D, h, Wk, bk, nullptr, k);
    sgemm_kernel<0><<<gD, blk>>>(NTOK, D, D, h, Wv, bv, nullptr, v);
    // attention
    flash_kernel<<<dim3(S / 64, H, B), blk>>>(q, k, v, am, ctx);
    // O projection + residual(x)
    sgemm_kernel<2><<<gD, blk>>>(NTOK, D, D, ctx, Wo, bo, x, x1);
    // LN2
    ln_kernel<<<NTOK, blk>>>(x1, ln2g, ln2b, h2);
    // FFN
    sgemm_kernel<1><<<gF, blk>>>(NTOK, DFF, D, h2, W1, b1, nullptr, ff);
    sgemm_kernel<2><<<gD, blk>>>(NTOK, D, DFF, ff, W2, b2, x1, out);
}

// round 2
// speedup vs baseline: 1.3434x; 1.3434x over previous
#include <cuda_runtime.h>
#include <math.h>
#include <stdint.h>

// Problem constants
static constexpr int D    = 768;
static constexpr int H    = 12;
static constexpr int HD   = 64;
static constexpr int DFF  = 3072;
static constexpr int B    = 2;
static constexpr int S    = 4096;
static constexpr int NTOK = B * S;   // 8192

// ---------------- scratch (static device globals; no allocation) ------------
__device__ float g_h  [NTOK * D];    // LN1 output
__device__ float g_q  [NTOK * D];
__device__ float g_k  [NTOK * D];
__device__ float g_v  [NTOK * D];
__device__ float g_ctx[NTOK * D];    // attention context
__device__ float g_x1 [NTOK * D];    // x + self-attn
__device__ float g_h2 [NTOK * D];    // LN2 output
__device__ float g_ff [NTOK * DFF];  // relu(h2@W1+b1)

// ---------------- LayerNorm: one block per row, 256 threads -----------------
__global__ __launch_bounds__(256) void ln_kernel(
    const float* __restrict__ x,
    const float* __restrict__ gamma,
    const float* __restrict__ beta,
    float* __restrict__ out)
{
    int row = blockIdx.x;
    int tid = threadIdx.x;
    const float* xr = x + (size_t)row * D;

    float v0 = xr[tid];
    float v1 = xr[tid + 256];
    float v2 = xr[tid + 512];
    float s  = v0 + v1 + v2;
    float ss = v0*v0 + v1*v1 + v2*v2;

    #pragma unroll
    for (int off = 16; off; off >>= 1) {
        s  += __shfl_down_sync(0xffffffffu, s,  off);
        ss += __shfl_down_sync(0xffffffffu, ss, off);
    }

    __shared__ float rs[8], rss[8];
    __shared__ float mu_s, rstd_s;
    if ((tid & 31) == 0) { rs[tid >> 5] = s; rss[tid >> 5] = ss; }
    __syncthreads();
    if (tid == 0) {
        float S_ = 0.f, SS_ = 0.f;
        #pragma unroll
        for (int w = 0; w < 8; w++) { S_ += rs[w]; SS_ += rss[w]; }
        float mu  = S_ * (1.0f / (float)D);
        float var = SS_ * (1.0f / (float)D) - mu * mu;
        mu_s   = mu;
        rstd_s = rsqrtf(var + 1e-5f);
    }
    __syncthreads();
    float mu = mu_s, r = rstd_s;

    float* orow = out + (size_t)row * D;
    orow[tid]       = (v0 - mu) * r * gamma[tid]       + beta[tid];
    orow[tid + 256] = (v1 - mu) * r * gamma[tid + 256] + beta[tid + 256];
    orow[tid + 512] = (v2 - mu) * r * gamma[tid + 512] + beta[tid + 512];
}

// ---------------- tf32 helpers ----------------------------------------------
__device__ __forceinline__ float tf32r(float x) {
    asm("cvt.rna.tf32.f32 %0, %0;" : "+f"(x));
    return x;
}

#define MMA_TF32(Cr, Ar, Br)                                                   \
    asm volatile(                                                              \
        "mma.sync.aligned.m16n8k8.row.col.f32.tf32.tf32.f32 "                  \
        "{%0,%1,%2,%3}, {%4,%5,%6,%7}, {%8,%9}, {%0,%1,%2,%3};"                \
        : "+f"(Cr[0]), "+f"(Cr[1]), "+f"(Cr[2]), "+f"(Cr[3])                   \
        : "r"(Ar[0]), "r"(Ar[1]), "r"(Ar[2]), "r"(Ar[3]),                      \
          "r"(Br[0]), "r"(Br[1]))

// ---------------- tf32 MMA GEMM: C = A[M,K] @ Bw[K,N] + bias ----------------
// 128x128 tile, BK=16, 8 warps (2x4), warp tile 64x32 (4x4 m16n8k8 atoms).
// EPI: 0 = bias, 1 = bias+relu, 2 = bias+residual
template <int EPI>
__global__ __launch_bounds__(256) void mma_gemm(
    int M, int N, int K,
    const float* __restrict__ A,
    const float* __restrict__ Bw,
    const float* __restrict__ bias,
    const float* __restrict__ res,
    float* __restrict__ C)
{
    constexpr int ASTR = 20;    // A smem stride: (20r + k) % 32 conflict-free
    constexpr int BSTR = 136;   // B smem stride: (8k + n) % 32 conflict-free
    __shared__ __align__(16) float As[2][128][ASTR];
    __shared__ __align__(16) float Bs[2][16][BSTR];

    int tid  = threadIdx.x;
    int lane = tid & 31;
    int warp = tid >> 5;
    int wm   = warp >> 2;       // 0..1
    int wn   = warp & 3;        // 0..3
    int gid  = lane >> 2;       // 0..7
    int tig  = lane & 3;        // 0..3

    int bx = blockIdx.x, by = blockIdx.y;
    const float* Ab = A  + (size_t)(by * 128) * K;
    const float* Bb = Bw + bx * 128;

    // global load mapping
    int arow = tid >> 2;            // 0..63 (and +64)
    int acol = (tid & 3) * 4;       // 0,4,8,12
    int brow = tid >> 4;            // 0..15
    int bcol = (tid & 15) * 4;      // 0..60 (and +64)

    float acc[4][4][4];
    #pragma unroll
    for (int i = 0; i < 4; i++)
        #pragma unroll
        for (int j = 0; j < 4; j++)
            #pragma unroll
            for (int r = 0; r < 4; r++) acc[i][j][r] = 0.f;

    int ntiles = K >> 4;

    // prologue: tile 0 -> smem buf 0
    {
        float4 a0 = *(const float4*)(Ab + (size_t)arow * K + acol);
        float4 a1 = *(const float4*)(Ab + (size_t)(arow + 64) * K + acol);
        float4 b0 = *(const float4*)(Bb + (size_t)brow * N + bcol);
        float4 b1 = *(const float4*)(Bb + (size_t)brow * N + bcol + 64);
        *(float4*)&As[0][arow][acol] =
            make_float4(tf32r(a0.x), tf32r(a0.y), tf32r(a0.z), tf32r(a0.w));
        *(float4*)&As[0][arow + 64][acol] =
            make_float4(tf32r(a1.x), tf32r(a1.y), tf32r(a1.z), tf32r(a1.w));
        *(float4*)&Bs[0][brow][bcol] =
            make_float4(tf32r(b0.x), tf32r(b0.y), tf32r(b0.z), tf32r(b0.w));
        *(float4*)&Bs[0][brow][bcol + 64] =
            make_float4(tf32r(b1.x), tf32r(b1.y), tf32r(b1.z), tf32r(b1.w));
    }
    __syncthreads();

    float4 ra0, ra1, rb0, rb1;
    for (int t = 0; t < ntiles; t++) {
        int buf = t & 1;
        bool more = (t + 1) < ntiles;
        if (more) {
            int k0 = (t + 1) << 4;
            ra0 = *(const float4*)(Ab + (size_t)arow * K + k0 + acol);
            ra1 = *(const float4*)(Ab + (size_t)(arow + 64) * K + k0 + acol);
            rb0 = *(const float4*)(Bb + (size_t)(k0 + brow) * N + bcol);
            rb1 = *(const float4*)(Bb + (size_t)(k0 + brow) * N + bcol + 64);
        }

        #pragma unroll
        for (int ks = 0; ks < 2; ks++) {
            int k0 = ks * 8;
            uint32_t af[4][4];
            uint32_t bf[4][2];
            #pragma unroll
            for (int ma = 0; ma < 4; ma++) {
                int r = wm * 64 + ma * 16 + gid;
                af[ma][0] = __float_as_uint(As[buf][r    ][k0 + tig]);
                af[ma][1] = __float_as_uint(As[buf][r + 8][k0 + tig]);
                af[ma][2] = __float_as_uint(As[buf][r    ][k0 + tig + 4]);
                af[ma][3] = __float_as_uint(As[buf][r + 8][k0 + tig + 4]);
            }
            #pragma unroll
            for (int na = 0; na < 4; na++) {
                int c = wn * 32 + na * 8 + gid;
                bf[na][0] = __float_as_uint(Bs[buf][k0 + tig    ][c]);
                bf[na][1] = __float_as_uint(Bs[buf][k0 + tig + 4][c]);
            }
            #pragma unroll
            for (int ma = 0; ma < 4; ma++)
                #pragma unroll
                for (int na = 0; na < 4; na++)
                    MMA_TF32(acc[ma][na], af[ma], bf[na]);
        }

        if (more) {
            int nb = buf ^ 1;
            *(float4*)&As[nb][arow][acol] =
                make_float4(tf32r(ra0.x), tf32r(ra0.y), tf32r(ra0.z), tf32r(ra0.w));
            *(float4*)&As[nb][arow + 64][acol] =
                make_float4(tf32r(ra1.x), tf32r(ra1.y), tf32r(ra1.z), tf32r(ra1.w));
            *(float4*)&Bs[nb][brow][bcol] =
                make_float4(tf32r(rb0.x), tf32r(rb0.y), tf32r(rb0.z), tf32r(rb0.w));
            *(float4*)&Bs[nb][brow][bcol + 64] =
                make_float4(tf32r(rb1.x), tf32r(rb1.y), tf32r(rb1.z), tf32r(rb1.w));
        }
        __syncthreads();
    }

    // epilogue
    #pragma unroll
    for (int ma = 0; ma < 4; ma++) {
        #pragma unroll
        for (int na = 0; na < 4; na++) {
            int row = by * 128 + wm * 64 + ma * 16 + gid;
            int col = bx * 128 + wn * 32 + na * 8 + 2 * tig;
            float b0v = bias[col], b1v = bias[col + 1];
            float v0 = acc[ma][na][0] + b0v;
            float v1 = acc[ma][na][1] + b1v;
            float v2 = acc[ma][na][2] + b0v;
            float v3 = acc[ma][na][3] + b1v;
            if (EPI == 1) {
                v0 = fmaxf(v0, 0.f); v1 = fmaxf(v1, 0.f);
                v2 = fmaxf(v2, 0.f); v3 = fmaxf(v3, 0.f);
            }
            if (EPI == 2) {
                const float* r0 = res + (size_t)row * N + col;
                const float* r1 = res + (size_t)(row + 8) * N + col;
                v0 += r0[0]; v1 += r0[1];
                v2 += r1[0]; v3 += r1[1];
            }
            *(float2*)(C + (size_t)row * N + col)       = make_float2(v0, v1);
            *(float2*)(C + (size_t)(row + 8) * N + col) = make_float2(v2, v3);
        }
    }
}

// ---------------- Flash attention (causal + key mask) -----------------------
// grid = (S/64, H, B), block = 256 threads.
__global__ __launch_bounds__(256, 1) void flash_kernel(
    const float* __restrict__ Q,
    const float* __restrict__ Kp,
    const float* __restrict__ Vp,
    const int*   __restrict__ am,
    float* __restrict__ O)
{
    __shared__ __align__(16) float Ks[64][HD + 4];
    __shared__ __align__(16) float Vs[64][HD + 4];
    __shared__ float addm[64];

    int qb = blockIdx.x;
    int h  = blockIdx.y;
    int b  = blockIdx.z;
    int tid  = threadIdx.x;
    int lane = tid & 31;
    int warp = tid >> 5;

    int rowl  = warp * 8 + (lane >> 2);  // 0..63 local query row
    int qpart = lane & 3;                // 0..3
    int qg    = qb * 64 + rowl;

    const float scale = 0.125f;          // 1/sqrt(64)

    float qreg[16];
    {
        const float* qptr = Q + ((size_t)b * S + qg) * D + h * HD + qpart * 16;
        #pragma unroll
        for (int i = 0; i < 16; i += 4) {
            float4 v = *(const float4*)(qptr + i);
            qreg[i + 0] = v.x * scale;
            qreg[i + 1] = v.y * scale;
            qreg[i + 2] = v.z * scale;
            qreg[i + 3] = v.w * scale;
        }
    }

    float m = -1e30f, l = 0.f;
    float acc[16];
    #pragma unroll
    for (int i = 0; i < 16; i++) acc[i] = 0.f;

    int nkv = qb + 1;
    for (int kv = 0; kv < nkv; kv++) {
        {
            int r = tid >> 2;
            int c = (tid & 3) * 16;
            const float* kp = Kp + ((size_t)b * S + kv * 64 + r) * D + h * HD + c;
            const float* vp = Vp + ((size_t)b * S + kv * 64 + r) * D + h * HD + c;
            #pragma unroll
            for (int i = 0; i < 16; i += 4) {
                *(float4*)&Ks[r][c + i] = *(const float4*)(kp + i);
                *(float4*)&Vs[r][c + i] = *(const float4*)(vp + i);
            }
            if (tid < 64)
                addm[tid] = (am[(size_t)b * S + kv * 64 + tid] != 0) ? 0.f : -1e30f;
        }
        __syncthreads();

        float s[64];
        #pragma unroll
        for (int j = 0; j < 64; j++) {
            float a = 0.f;
            #pragma unroll
            for (int kk = 0; kk < 16; kk++)
                a += qreg[kk] * Ks[j][qpart * 16 + kk];
            s[j] = a;
        }
        #pragma unroll
        for (int j = 0; j < 64; j++) {
            s[j] += __shfl_xor_sync(0xffffffffu, s[j], 1);
            s[j] += __shfl_xor_sync(0xffffffffu, s[j], 2);
        }

        // masking: additive key mask always; causal only on the diagonal block
        float mb = -1e30f;
        if (kv == qb) {
            #pragma unroll
            for (int j = 0; j < 64; j++) {
                s[j] = (j <= rowl) ? s[j] + addm[j] : -1e30f;
                mb = fmaxf(mb, s[j]);
            }
        } else {
            #pragma unroll
            for (int j = 0; j < 64; j++) {
                s[j] += addm[j];
                mb = fmaxf(mb, s[j]);
            }
        }

        float mnew = fmaxf(m, mb);
        float corr = __expf(m - mnew);
        float psum = 0.f;
        #pragma unroll
        for (int j = 0; j < 64; j++) {
            s[j] = __expf(s[j] - mnew);
            psum += s[j];
        }
        m = mnew;
        l = l * corr + psum;

        #pragma unroll
        for (int dd = 0; dd < 16; dd++) acc[dd] *= corr;

        #pragma unroll
        for (int j = 0; j < 64; j++) {
            float pj = s[j];
            #pragma unroll
            for (int dd = 0; dd < 16; dd++)
                acc[dd] += pj * Vs[j][qpart * 16 + dd];
        }
        __syncthreads();
    }

    float inv = 1.0f / l;
    float* optr = O + ((size_t)b * S + qg) * D + h * HD + qpart * 16;
    #pragma unroll
    for (int dd = 0; dd < 16; dd += 4) {
        *(float4*)(optr + dd) = make_float4(acc[dd] * inv, acc[dd+1] * inv,
                                            acc[dd+2] * inv, acc[dd+3] * inv);
    }
}

// ---------------- launch ----------------------------------------------------
extern "C" void kernel_launch(void* const* d_in, const int* in_sizes, int n_in,
                              void* d_out, int out_size)
{
    const float* x    = (const float*)d_in[0];
    const int*   am   = (const int*)  d_in[1];
    const float* ln1g = (const float*)d_in[2];
    const float* ln1b = (const float*)d_in[3];
    const float* ln2g = (const float*)d_in[4];
    const float* ln2b = (const float*)d_in[5];
    const float* Wq   = (const float*)d_in[6];
    const float* bq   = (const float*)d_in[7];
    const float* Wk   = (const float*)d_in[8];
    const float* bk   = (const float*)d_in[9];
    const float* Wv   = (const float*)d_in[10];
    const float* bv   = (const float*)d_in[11];
    const float* Wo   = (const float*)d_in[12];
    const float* bo   = (const float*)d_in[13];
    const float* W1   = (const float*)d_in[14];
    const float* b1   = (const float*)d_in[15];
    const float* W2   = (const float*)d_in[16];
    const float* b2   = (const float*)d_in[17];
    float* out = (float*)d_out;

    float *h, *q, *k, *v, *ctx, *x1, *h2, *ff;
    cudaGetSymbolAddress((void**)&h,   g_h);
    cudaGetSymbolAddress((void**)&q,   g_q);
    cudaGetSymbolAddress((void**)&k,   g_k);
    cudaGetSymbolAddress((void**)&v,   g_v);
    cudaGetSymbolAddress((void**)&ctx, g_ctx);
    cudaGetSymbolAddress((void**)&x1,  g_x1);
    cudaGetSymbolAddress((void**)&h2,  g_h2);
    cudaGetSymbolAddress((void**)&ff,  g_ff);

    dim3 blk(256);
    dim3 gD(D / 128, NTOK / 128);      // N=768 GEMMs
    dim3 gF(DFF / 128, NTOK / 128);    // N=3072 GEMM

    // LN1
    ln_kernel<<<NTOK, blk>>>(x, ln1g, ln1b, h);
    // QKV projections
    mma_gemm<0><<<gD, blk>>>(NTOK, D, D, h, Wq, bq, nullptr, q);
    mma_gemm<0><<<gD, blk>>>(NTOK, D, D, h, Wk, bk, nullptr, k);
    mma_gemm<0><<<gD, blk>>>(NTOK, D, D, h, Wv, bv, nullptr, v);
    // attention
    flash_kernel<<<dim3(S / 64, H, B), blk>>>(q, k, v, am, ctx);
    // O projection + residual(x)
    mma_gemm<2><<<gD, blk>>>(NTOK, D, D, ctx, Wo, bo, x, x1);
    // LN2
    ln_kernel<<<NTOK, blk>>>(x1, ln2g, ln2b, h2);
    // FFN
    mma_gemm<1><<<gF, blk>>>(NTOK, DFF, D, h2, W1, b1, nullptr, ff);
    mma_gemm<2><<<gD, blk>>>(NTOK, D, DFF, ff, W2, b2, x1, out);
}

// round 3
// speedup vs baseline: 5.7616x; 4.2889x over previous
#include <cuda_runtime.h>
#include <math.h>
#include <stdint.h>

// Problem constants
static constexpr int D    = 768;
static constexpr int H    = 12;
static constexpr int HD   = 64;
static constexpr int DFF  = 3072;
static constexpr int B    = 2;
static constexpr int S    = 4096;
static constexpr int NTOK = B * S;   // 8192

// ---------------- scratch (static device globals; no allocation) ------------
__device__ float g_h  [NTOK * D];    // LN1 output
__device__ float g_q  [NTOK * D];
__device__ float g_k  [NTOK * D];
__device__ float g_v  [NTOK * D];
__device__ float g_ctx[NTOK * D];    // attention context
__device__ float g_x1 [NTOK * D];    // x + self-attn
__device__ float g_h2 [NTOK * D];    // LN2 output
__device__ float g_ff [NTOK * DFF];  // relu(h2@W1+b1)

// ---------------- LayerNorm: one block per row, 256 threads -----------------
__global__ __launch_bounds__(256) void ln_kernel(
    const float* __restrict__ x,
    const float* __restrict__ gamma,
    const float* __restrict__ beta,
    float* __restrict__ out)
{
    int row = blockIdx.x;
    int tid = threadIdx.x;
    const float* xr = x + (size_t)row * D;

    float v0 = xr[tid];
    float v1 = xr[tid + 256];
    float v2 = xr[tid + 512];
    float s  = v0 + v1 + v2;
    float ss = v0*v0 + v1*v1 + v2*v2;

    #pragma unroll
    for (int off = 16; off; off >>= 1) {
        s  += __shfl_down_sync(0xffffffffu, s,  off);
        ss += __shfl_down_sync(0xffffffffu, ss, off);
    }

    __shared__ float rs[8], rss[8];
    __shared__ float mu_s, rstd_s;
    if ((tid & 31) == 0) { rs[tid >> 5] = s; rss[tid >> 5] = ss; }
    __syncthreads();
    if (tid == 0) {
        float S_ = 0.f, SS_ = 0.f;
        #pragma unroll
        for (int w = 0; w < 8; w++) { S_ += rs[w]; SS_ += rss[w]; }
        float mu  = S_ * (1.0f / (float)D);
        float var = SS_ * (1.0f / (float)D) - mu * mu;
        mu_s   = mu;
        rstd_s = rsqrtf(var + 1e-5f);
    }
    __syncthreads();
    float mu = mu_s, r = rstd_s;

    float* orow = out + (size_t)row * D;
    orow[tid]       = (v0 - mu) * r * gamma[tid]       + beta[tid];
    orow[tid + 256] = (v1 - mu) * r * gamma[tid + 256] + beta[tid + 256];
    orow[tid + 512] = (v2 - mu) * r * gamma[tid + 512] + beta[tid + 512];
}

// ---------------- tf32 helpers ----------------------------------------------
__device__ __forceinline__ float tf32r(float x) {
    asm("cvt.rna.tf32.f32 %0, %0;" : "+f"(x));
    return x;
}
__device__ __forceinline__ uint32_t tf32u(float x) {
    asm("cvt.rna.tf32.f32 %0, %0;" : "+f"(x));
    return __float_as_uint(x);
}

#define MMA_TF32(Cr, Ar, B0, B1)                                               \
    asm volatile(                                                              \
        "mma.sync.aligned.m16n8k8.row.col.f32.tf32.tf32.f32 "                  \
        "{%0,%1,%2,%3}, {%4,%5,%6,%7}, {%8,%9}, {%0,%1,%2,%3};"                \
        : "+f"(Cr[0]), "+f"(Cr[1]), "+f"(Cr[2]), "+f"(Cr[3])                   \
        : "r"(Ar[0]), "r"(Ar[1]), "r"(Ar[2]), "r"(Ar[3]),                      \
          "r"(B0), "r"(B1))

// ---------------- tf32 MMA GEMM: C = A[M,K] @ Bw[K,N] + bias ----------------
// 128x128 tile, BK=16, 8 warps (2x4), warp tile 64x32 (4x4 m16n8k8 atoms).
// EPI: 0 = bias, 1 = bias+relu, 2 = bias+residual
template <int EPI>
__global__ __launch_bounds__(256) void mma_gemm(
    int M, int N, int K,
    const float* __restrict__ A,
    const float* __restrict__ Bw,
    const float* __restrict__ bias,
    const float* __restrict__ res,
    float* __restrict__ C)
{
    constexpr int ASTR = 20;
    constexpr int BSTR = 136;
    __shared__ __align__(16) float As[2][128][ASTR];
    __shared__ __align__(16) float Bs[2][16][BSTR];

    int tid  = threadIdx.x;
    int lane = tid & 31;
    int warp = tid >> 5;
    int wm   = warp >> 2;
    int wn   = warp & 3;
    int gid  = lane >> 2;
    int tig  = lane & 3;

    int bx = blockIdx.x, by = blockIdx.y;
    const float* Ab = A  + (size_t)(by * 128) * K;
    const float* Bb = Bw + bx * 128;

    int arow = tid >> 2;
    int acol = (tid & 3) * 4;
    int brow = tid >> 4;
    int bcol = (tid & 15) * 4;

    float acc[4][4][4];
    #pragma unroll
    for (int i = 0; i < 4; i++)
        #pragma unroll
        for (int j = 0; j < 4; j++)
            #pragma unroll
            for (int r = 0; r < 4; r++) acc[i][j][r] = 0.f;

    int ntiles = K >> 4;

    {
        float4 a0 = *(const float4*)(Ab + (size_t)arow * K + acol);
        float4 a1 = *(const float4*)(Ab + (size_t)(arow + 64) * K + acol);
        float4 b0 = *(const float4*)(Bb + (size_t)brow * N + bcol);
        float4 b1 = *(const float4*)(Bb + (size_t)brow * N + bcol + 64);
        *(float4*)&As[0][arow][acol] =
            make_float4(tf32r(a0.x), tf32r(a0.y), tf32r(a0.z), tf32r(a0.w));
        *(float4*)&As[0][arow + 64][acol] =
            make_float4(tf32r(a1.x), tf32r(a1.y), tf32r(a1.z), tf32r(a1.w));
        *(float4*)&Bs[0][brow][bcol] =
            make_float4(tf32r(b0.x), tf32r(b0.y), tf32r(b0.z), tf32r(b0.w));
        *(float4*)&Bs[0][brow][bcol + 64] =
            make_float4(tf32r(b1.x), tf32r(b1.y), tf32r(b1.z), tf32r(b1.w));
    }
    __syncthreads();

    float4 ra0, ra1, rb0, rb1;
    for (int t = 0; t < ntiles; t++) {
        int buf = t & 1;
        bool more = (t + 1) < ntiles;
        if (more) {
            int k0 = (t + 1) << 4;
            ra0 = *(const float4*)(Ab + (size_t)arow * K + k0 + acol);
            ra1 = *(const float4*)(Ab + (size_t)(arow + 64) * K + k0 + acol);
            rb0 = *(const float4*)(Bb + (size_t)(k0 + brow) * N + bcol);
            rb1 = *(const float4*)(Bb + (size_t)(k0 + brow) * N + bcol + 64);
        }

        #pragma unroll
        for (int ks = 0; ks < 2; ks++) {
            int k0 = ks * 8;
            uint32_t af[4][4];
            uint32_t bf[4][2];
            #pragma unroll
            for (int ma = 0; ma < 4; ma++) {
                int r = wm * 64 + ma * 16 + gid;
                af[ma][0] = __float_as_uint(As[buf][r    ][k0 + tig]);
                af[ma][1] = __float_as_uint(As[buf][r + 8][k0 + tig]);
                af[ma][2] = __float_as_uint(As[buf][r    ][k0 + tig + 4]);
                af[ma][3] = __float_as_uint(As[buf][r + 8][k0 + tig + 4]);
            }
            #pragma unroll
            for (int na = 0; na < 4; na++) {
                int c = wn * 32 + na * 8 + gid;
                bf[na][0] = __float_as_uint(Bs[buf][k0 + tig    ][c]);
                bf[na][1] = __float_as_uint(Bs[buf][k0 + tig + 4][c]);
            }
            #pragma unroll
            for (int ma = 0; ma < 4; ma++)
                #pragma unroll
                for (int na = 0; na < 4; na++)
                    MMA_TF32(acc[ma][na], af[ma], bf[na][0], bf[na][1]);
        }

        if (more) {
            int nb = buf ^ 1;
            *(float4*)&As[nb][arow][acol] =
                make_float4(tf32r(ra0.x), tf32r(ra0.y), tf32r(ra0.z), tf32r(ra0.w));
            *(float4*)&As[nb][arow + 64][acol] =
                make_float4(tf32r(ra1.x), tf32r(ra1.y), tf32r(ra1.z), tf32r(ra1.w));
            *(float4*)&Bs[nb][brow][bcol] =
                make_float4(tf32r(rb0.x), tf32r(rb0.y), tf32r(rb0.z), tf32r(rb0.w));
            *(float4*)&Bs[nb][brow][bcol + 64] =
                make_float4(tf32r(rb1.x), tf32r(rb1.y), tf32r(rb1.z), tf32r(rb1.w));
        }
        __syncthreads();
    }

    #pragma unroll
    for (int ma = 0; ma < 4; ma++) {
        #pragma unroll
        for (int na = 0; na < 4; na++) {
            int row = by * 128 + wm * 64 + ma * 16 + gid;
            int col = bx * 128 + wn * 32 + na * 8 + 2 * tig;
            float b0v = bias[col], b1v = bias[col + 1];
            float v0 = acc[ma][na][0] + b0v;
            float v1 = acc[ma][na][1] + b1v;
            float v2 = acc[ma][na][2] + b0v;
            float v3 = acc[ma][na][3] + b1v;
            if (EPI == 1) {
                v0 = fmaxf(v0, 0.f); v1 = fmaxf(v1, 0.f);
                v2 = fmaxf(v2, 0.f); v3 = fmaxf(v3, 0.f);
            }
            if (EPI == 2) {
                const float* r0 = res + (size_t)row * N + col;
                const float* r1 = res + (size_t)(row + 8) * N + col;
                v0 += r0[0]; v1 += r0[1];
                v2 += r1[0]; v3 += r1[1];
            }
            *(float2*)(C + (size_t)row * N + col)       = make_float2(v0, v1);
            *(float2*)(C + (size_t)(row + 8) * N + col) = make_float2(v2, v3);
        }
    }
}

// ---------------- Flash attention, tf32 tensor cores ------------------------
// grid = (S/128, H, B), block = 256 (8 warps). Warp w owns query rows
// [qb*128 + w*16, +16). KV tiles of 64 keys staged in smem.
__global__ __launch_bounds__(256, 1) void flash_mma(
    const float* __restrict__ Q,
    const float* __restrict__ Kp,
    const float* __restrict__ Vp,
    const int*   __restrict__ am,
    float* __restrict__ O)
{
    constexpr int KSTR = 68;   // smem stride; frag reads proven conflict-free
    __shared__ __align__(16) float Ks[64][KSTR];
    __shared__ __align__(16) float Vs[64][KSTR];
    __shared__ float addm[64];

    const unsigned FULL = 0xffffffffu;
    int qb = blockIdx.x, h = blockIdx.y, b = blockIdx.z;
    int tid  = threadIdx.x;
    int lane = tid & 31;
    int warp = tid >> 5;
    int gid  = lane >> 2;   // 0..7
    int tig  = lane & 3;    // 0..3

    int row0 = qb * 128 + warp * 16;
    int r1 = row0 + gid;        // this thread's two query rows (global)
    int r2 = r1 + 8;
    int wrow_max = row0 + 15;

    const float scale = 0.125f;  // 1/sqrt(64)

    // Q fragments (held in registers for the whole kernel), pre-scaled tf32
    uint32_t qa[8][4];
    {
        const float* q1 = Q + ((size_t)b * S + r1) * D + h * HD;
        const float* q2 = Q + ((size_t)b * S + r2) * D + h * HD;
        #pragma unroll
        for (int ka = 0; ka < 8; ka++) {
            qa[ka][0] = tf32u(q1[ka * 8 + tig]     * scale);
            qa[ka][1] = tf32u(q2[ka * 8 + tig]     * scale);
            qa[ka][2] = tf32u(q1[ka * 8 + tig + 4] * scale);
            qa[ka][3] = tf32u(q2[ka * 8 + tig + 4] * scale);
        }
    }

    float m1 = -1e30f, m2 = -1e30f, l1 = 0.f, l2 = 0.f;
    float oacc[8][4];
    #pragma unroll
    for (int i = 0; i < 8; i++)
        #pragma unroll
        for (int j = 0; j < 4; j++) oacc[i][j] = 0.f;

    int ntiles = qb * 2 + 2;   // causal frontier for this block
    for (int kv = 0; kv < ntiles; kv++) {
        // ---- cooperative K/V tile load (tf32-rounded) ----
        {
            int r = tid >> 2;
            int c = (tid & 3) * 16;
            const float* kp = Kp + ((size_t)b * S + kv * 64 + r) * D + h * HD + c;
            const float* vp = Vp + ((size_t)b * S + kv * 64 + r) * D + h * HD + c;
            #pragma unroll
            for (int i = 0; i < 16; i += 4) {
                float4 kx = *(const float4*)(kp + i);
                float4 vx = *(const float4*)(vp + i);
                *(float4*)&Ks[r][c + i] =
                    make_float4(tf32r(kx.x), tf32r(kx.y), tf32r(kx.z), tf32r(kx.w));
                *(float4*)&Vs[r][c + i] =
                    make_float4(tf32r(vx.x), tf32r(vx.y), tf32r(vx.z), tf32r(vx.w));
            }
            if (tid < 64)
                addm[tid] = (am[(size_t)b * S + kv * 64 + tid] != 0) ? 0.f : -1e30f;
        }
        __syncthreads();

        if (kv * 64 <= wrow_max) {  // warp-uniform causal skip
            // ---- S = Q @ K^T (16x64 per warp) ----
            float sc[8][4];
            #pragma unroll
            for (int na = 0; na < 8; na++)
                #pragma unroll
                for (int j = 0; j < 4; j++) sc[na][j] = 0.f;

            #pragma unroll
            for (int ka = 0; ka < 8; ka++) {
                #pragma unroll
                for (int na = 0; na < 8; na++) {
                    uint32_t b0 = __float_as_uint(Ks[na * 8 + gid][ka * 8 + tig]);
                    uint32_t b1 = __float_as_uint(Ks[na * 8 + gid][ka * 8 + tig + 4]);
                    MMA_TF32(sc[na], qa[ka], b0, b1);
                }
            }

            // ---- mask (causal + key mask) + row max ----
            float mt1 = -1e30f, mt2 = -1e30f;
            #pragma unroll
            for (int na = 0; na < 8; na++) {
                int key0 = kv * 64 + na * 8 + 2 * tig;
                float a0 = addm[na * 8 + 2 * tig];
                float a1 = addm[na * 8 + 2 * tig + 1];
                sc[na][0] = (key0     <= r1) ? sc[na][0] + a0 : -1e30f;
                sc[na][1] = (key0 + 1 <= r1) ? sc[na][1] + a1 : -1e30f;
                sc[na][2] = (key0     <= r2) ? sc[na][2] + a0 : -1e30f;
                sc[na][3] = (key0 + 1 <= r2) ? sc[na][3] + a1 : -1e30f;
                mt1 = fmaxf(mt1, fmaxf(sc[na][0], sc[na][1]));
                mt2 = fmaxf(mt2, fmaxf(sc[na][2], sc[na][3]));
            }
            mt1 = fmaxf(mt1, __shfl_xor_sync(FULL, mt1, 1));
            mt1 = fmaxf(mt1, __shfl_xor_sync(FULL, mt1, 2));
            mt2 = fmaxf(mt2, __shfl_xor_sync(FULL, mt2, 1));
            mt2 = fmaxf(mt2, __shfl_xor_sync(FULL, mt2, 2));

            float mn1 = fmaxf(m1, mt1);
            float mn2 = fmaxf(m2, mt2);
            float c1 = __expf(m1 - mn1);
            float c2 = __expf(m2 - mn2);
            m1 = mn1; m2 = mn2;

            // ---- exp + P conversion (C-frag -> A-frag via quad shuffles) ----
            int basel = lane & ~3;
            int srcA  = basel + (tig >> 1);
            int srcB  = srcA + 2;
            int comp  = tig & 1;
            uint32_t pa[8][4];
            float pt1 = 0.f, pt2 = 0.f;
            #pragma unroll
            for (int na = 0; na < 8; na++) {
                float e0 = __expf(sc[na][0] - mn1);
                float e1 = __expf(sc[na][1] - mn1);
                float e2 = __expf(sc[na][2] - mn2);
                float e3 = __expf(sc[na][3] - mn2);
                pt1 += e0 + e1;
                pt2 += e2 + e3;
                float x0 = __shfl_sync(FULL, e0, srcA);
                float x1 = __shfl_sync(FULL, e1, srcA);
                float y0 = __shfl_sync(FULL, e2, srcA);
                float y1 = __shfl_sync(FULL, e3, srcA);
                float z0 = __shfl_sync(FULL, e0, srcB);
                float z1 = __shfl_sync(FULL, e1, srcB);
                float w0 = __shfl_sync(FULL, e2, srcB);
                float w1 = __shfl_sync(FULL, e3, srcB);
                pa[na][0] = __float_as_uint(comp ? x1 : x0);
                pa[na][1] = __float_as_uint(comp ? y1 : y0);
                pa[na][2] = __float_as_uint(comp ? z1 : z0);
                pa[na][3] = __float_as_uint(comp ? w1 : w0);
            }
            pt1 += __shfl_xor_sync(FULL, pt1, 1);
            pt1 += __shfl_xor_sync(FULL, pt1, 2);
            pt2 += __shfl_xor_sync(FULL, pt2, 1);
            pt2 += __shfl_xor_sync(FULL, pt2, 2);
            l1 = l1 * c1 + pt1;
            l2 = l2 * c2 + pt2;

            // ---- rescale O accumulators ----
            #pragma unroll
            for (int na = 0; na < 8; na++) {
                oacc[na][0] *= c1; oacc[na][1] *= c1;
                oacc[na][2] *= c2; oacc[na][3] *= c2;
            }

            // ---- O += P @ V ----
            #pragma unroll
            for (int ka = 0; ka < 8; ka++) {
                #pragma unroll
                for (int na = 0; na < 8; na++) {
                    uint32_t b0 = __float_as_uint(Vs[ka * 8 + tig    ][na * 8 + gid]);
                    uint32_t b1 = __float_as_uint(Vs[ka * 8 + tig + 4][na * 8 + gid]);
                    MMA_TF32(oacc[na], pa[ka], b0, b1);
                }
            }
        }
        __syncthreads();
    }

    float inv1 = 1.0f / l1;
    float inv2 = 1.0f / l2;
    float* o1 = O + ((size_t)b * S + r1) * D + h * HD;
    float* o2 = O + ((size_t)b * S + r2) * D + h * HD;
    #pragma unroll
    for (int na = 0; na < 8; na++) {
        int col = na * 8 + 2 * tig;
        *(float2*)(o1 + col) = make_float2(oacc[na][0] * inv1, oacc[na][1] * inv1);
        *(float2*)(o2 + col) = make_float2(oacc[na][2] * inv2, oacc[na][3] * inv2);
    }
}

// ---------------- launch ----------------------------------------------------
extern "C" void kernel_launch(void* const* d_in, const int* in_sizes, int n_in,
                              void* d_out, int out_size)
{
    const float* x    = (const float*)d_in[0];
    const int*   am   = (const int*)  d_in[1];
    const float* ln1g = (const float*)d_in[2];
    const float* ln1b = (const float*)d_in[3];
    const float* ln2g = (const float*)d_in[4];
    const float* ln2b = (const float*)d_in[5];
    const float* Wq   = (const float*)d_in[6];
    const float* bq   = (const float*)d_in[7];
    const float* Wk   = (const float*)d_in[8];
    const float* bk   = (const float*)d_in[9];
    const float* Wv   = (const float*)d_in[10];
    const float* bv   = (const float*)d_in[11];
    const float* Wo   = (const float*)d_in[12];
    const float* bo   = (const float*)d_in[13];
    const float* W1   = (const float*)d_in[14];
    const float* b1   = (const float*)d_in[15];
    const float* W2   = (const float*)d_in[16];
    const float* b2   = (const float*)d_in[17];
    float* out = (float*)d_out;

    float *h, *q, *k, *v, *ctx, *x1, *h2, *ff;
    cudaGetSymbolAddress((void**)&h,   g_h);
    cudaGetSymbolAddress((void**)&q,   g_q);
    cudaGetSymbolAddress((void**)&k,   g_k);
    cudaGetSymbolAddress((void**)&v,   g_v);
    cudaGetSymbolAddress((void**)&ctx, g_ctx);
    cudaGetSymbolAddress((void**)&x1,  g_x1);
    cudaGetSymbolAddress((void**)&h2,  g_h2);
    cudaGetSymbolAddress((void**)&ff,  g_ff);

    dim3 blk(256);
    dim3 gD(D / 128, NTOK / 128);      // N=768 GEMMs
    dim3 gF(DFF / 128, NTOK / 128);    // N=3072 GEMM

    // LN1
    ln_kernel<<<NTOK, blk>>>(x, ln1g, ln1b, h);
    // QKV projections
    mma_gemm<0><<<gD, blk>>>(NTOK, D, D, h, Wq, bq, nullptr, q);
    mma_gemm<0><<<gD, blk>>>(NTOK, D, D, h, Wk, bk, nullptr, k);
    mma_gemm<0><<<gD, blk>>>(NTOK, D, D, h, Wv, bv, nullptr, v);
    // attention (tensor-core flash)
    flash_mma<<<dim3(S / 128, H, B), blk>>>(q, k, v, am, ctx);
    // O projection + residual(x)
    mma_gemm<2><<<gD, blk>>>(NTOK, D, D, ctx, Wo, bo, x, x1);
    // LN2
    ln_kernel<<<NTOK, blk>>>(x1, ln2g, ln2b, h2);
    // FFN
    mma_gemm<1><<<gF, blk>>>(NTOK, DFF, D, h2, W1, b1, nullptr, ff);
    mma_gemm<2><<<gD, blk>>>(NTOK, D, DFF, ff, W2, b2, x1, out);
}

// round 6
// speedup vs baseline: 6.7761x; 1.1761x over previous
#include <cuda_runtime.h>
#include <math.h>
#include <stdint.h>

// Problem constants
static constexpr int D    = 768;
static constexpr int H    = 12;
static constexpr int HD   = 64;
static constexpr int DFF  = 3072;
static constexpr int B    = 2;
static constexpr int S    = 4096;
static constexpr int NTOK = B * S;   // 8192

// ---------------- scratch (static device globals; no allocation) ------------
__device__ float g_h  [NTOK * D];
__device__ float g_q  [NTOK * D];
__device__ float g_k  [NTOK * D];
__device__ float g_v  [NTOK * D];
__device__ float g_ctx[NTOK * D];
__device__ float g_x1 [NTOK * D];
__device__ float g_h2 [NTOK * D];
__device__ float g_ff [NTOK * DFF];

// ---------------- cp.async helpers ------------------------------------------
#define CP16(dst_u32, src_ptr)                                                 \
    asm volatile("cp.async.cg.shared.global [%0], [%1], 16;"                   \
                 :: "r"(dst_u32), "l"(src_ptr))
#define CP_COMMIT() asm volatile("cp.async.commit_group;")
#define CP_WAIT(N)  asm volatile("cp.async.wait_group %0;" :: "n"(N))

// ---------------- LayerNorm: one block per row, 256 threads -----------------
__global__ __launch_bounds__(256) void ln_kernel(
    const float* __restrict__ x,
    const float* __restrict__ gamma,
    const float* __restrict__ beta,
    float* __restrict__ out)
{
    int row = blockIdx.x;
    int tid = threadIdx.x;
    const float* xr = x + (size_t)row * D;

    float v0 = xr[tid];
    float v1 = xr[tid + 256];
    float v2 = xr[tid + 512];
    float s  = v0 + v1 + v2;
    float ss = v0*v0 + v1*v1 + v2*v2;

    #pragma unroll
    for (int off = 16; off; off >>= 1) {
        s  += __shfl_down_sync(0xffffffffu, s,  off);
        ss += __shfl_down_sync(0xffffffffu, ss, off);
    }

    __shared__ float rs[8], rss[8];
    __shared__ float mu_s, rstd_s;
    if ((tid & 31) == 0) { rs[tid >> 5] = s; rss[tid >> 5] = ss; }
    __syncthreads();
    if (tid == 0) {
        float S_ = 0.f, SS_ = 0.f;
        #pragma unroll
        for (int w = 0; w < 8; w++) { S_ += rs[w]; SS_ += rss[w]; }
        float mu  = S_ * (1.0f / (float)D);
        float var = SS_ * (1.0f / (float)D) - mu * mu;
        mu_s   = mu;
        rstd_s = rsqrtf(var + 1e-5f);
    }
    __syncthreads();
    float mu = mu_s, r = rstd_s;

    float* orow = out + (size_t)row * D;
    orow[tid]       = (v0 - mu) * r * gamma[tid]       + beta[tid];
    orow[tid + 256] = (v1 - mu) * r * gamma[tid + 256] + beta[tid + 256];
    orow[tid + 512] = (v2 - mu) * r * gamma[tid + 512] + beta[tid + 512];
}

// ---------------- tf32 helpers ----------------------------------------------
__device__ __forceinline__ uint32_t tf32u(float x) {
    asm("cvt.rna.tf32.f32 %0, %0;" : "+f"(x));
    return __float_as_uint(x);
}

#define MMA_TF32(Cr, Ar, B0, B1)                                               \
    asm volatile(                                                              \
        "mma.sync.aligned.m16n8k8.row.col.f32.tf32.tf32.f32 "                  \
        "{%0,%1,%2,%3}, {%4,%5,%6,%7}, {%8,%9}, {%0,%1,%2,%3};"                \
        : "+f"(Cr[0]), "+f"(Cr[1]), "+f"(Cr[2]), "+f"(Cr[3])                   \
        : "r"(Ar[0]), "r"(Ar[1]), "r"(Ar[2]), "r"(Ar[3]),                      \
          "r"(B0), "r"(B1))

// ---------------- tf32 MMA GEMM, cp.async 3-stage pipeline ------------------
// 128x128 tile, BK=16, 8 warps (2x4), warp tile 64x32.
// EPI: 0 = bias, 1 = bias+relu, 2 = bias+residual
static constexpr int GA_STR = 20;
static constexpr int GB_STR = 136;
static constexpr int GA_SZ  = 128 * GA_STR;           // floats per A stage
static constexpr int GB_SZ  = 16 * GB_STR;            // floats per B stage
static constexpr int G_STG  = GA_SZ + GB_SZ;          // floats per stage
static constexpr int GEMM_SMEM = 3 * G_STG * 4;       // bytes

template <int EPI>
__global__ __launch_bounds__(256, 2) void mma_gemm(
    int M, int N, int K,
    const float* __restrict__ A,
    const float* __restrict__ Bw,
    const float* __restrict__ bias,
    const float* __restrict__ res,
    float* __restrict__ C)
{
    extern __shared__ float sm[];

    int tid  = threadIdx.x;
    int lane = tid & 31;
    int warp = tid >> 5;
    int wm   = warp >> 2;
    int wn   = warp & 3;
    int gid  = lane >> 2;
    int tig  = lane & 3;

    int bx = blockIdx.x, by = blockIdx.y;
    const float* Ab = A  + (size_t)(by * 128) * K;
    const float* Bb = Bw + bx * 128;

    int arow = tid >> 2;            // 0..63 (+64)
    int acol = (tid & 3) * 4;
    int brow = tid >> 4;            // 0..15
    int bcol = (tid & 15) * 4;      // 0..60 (+64)

    const float* ag0 = Ab + (size_t)arow * K + acol;
    const float* ag1 = Ab + (size_t)(arow + 64) * K + acol;
    const float* bg0 = Bb + (size_t)brow * N + bcol;

    uint32_t smb = (uint32_t)__cvta_generic_to_shared(sm);
    uint32_t aoff0 = (arow * GA_STR + acol) * 4;
    uint32_t aoff1 = ((arow + 64) * GA_STR + acol) * 4;
    uint32_t boff0 = (GA_SZ + brow * GB_STR + bcol) * 4;
    uint32_t boff1 = boff0 + 64 * 4;

    auto issue = [&](int t) {
        uint32_t s = smb + (uint32_t)((t % 3) * G_STG * 4);
        CP16(s + aoff0, ag0 + t * 16);
        CP16(s + aoff1, ag1 + t * 16);
        const float* bp = bg0 + (size_t)t * 16 * N;
        CP16(s + boff0, bp);
        CP16(s + boff1, bp + 64);
        CP_COMMIT();
    };

    float acc[4][4][4];
    #pragma unroll
    for (int i = 0; i < 4; i++)
        #pragma unroll
        for (int j = 0; j < 4; j++)
            #pragma unroll
            for (int r = 0; r < 4; r++) acc[i][j][r] = 0.f;

    int ntiles = K >> 4;
    issue(0);
    issue(1);

    for (int t = 0; t < ntiles; t++) {
        if (t + 1 < ntiles) { CP_WAIT(1); } else { CP_WAIT(0); }
        __syncthreads();
        if (t + 2 < ntiles) issue(t + 2);

        const float* As = sm + (t % 3) * G_STG;
        const float* Bs = As + GA_SZ;

        #pragma unroll
        for (int ks = 0; ks < 2; ks++) {
            int k0 = ks * 8;
            uint32_t af[4][4];
            uint32_t bf[4][2];
            #pragma unroll
            for (int ma = 0; ma < 4; ma++) {
                int r = wm * 64 + ma * 16 + gid;
                af[ma][0] = __float_as_uint(As[r * GA_STR + k0 + tig]);
                af[ma][1] = __float_as_uint(As[(r + 8) * GA_STR + k0 + tig]);
                af[ma][2] = __float_as_uint(As[r * GA_STR + k0 + tig + 4]);
                af[ma][3] = __float_as_uint(As[(r + 8) * GA_STR + k0 + tig + 4]);
            }
            #pragma unroll
            for (int na = 0; na < 4; na++) {
                int c = wn * 32 + na * 8 + gid;
                bf[na][0] = __float_as_uint(Bs[(k0 + tig) * GB_STR + c]);
                bf[na][1] = __float_as_uint(Bs[(k0 + tig + 4) * GB_STR + c]);
            }
            #pragma unroll
            for (int ma = 0; ma < 4; ma++)
                #pragma unroll
                for (int na = 0; na < 4; na++)
                    MMA_TF32(acc[ma][na], af[ma], bf[na][0], bf[na][1]);
        }
        __syncthreads();
    }

    #pragma unroll
    for (int ma = 0; ma < 4; ma++) {
        #pragma unroll
        for (int na = 0; na < 4; na++) {
            int row = by * 128 + wm * 64 + ma * 16 + gid;
            int col = bx * 128 + wn * 32 + na * 8 + 2 * tig;
            float b0v = bias[col], b1v = bias[col + 1];
            float v0 = acc[ma][na][0] + b0v;
            float v1 = acc[ma][na][1] + b1v;
            float v2 = acc[ma][na][2] + b0v;
            float v3 = acc[ma][na][3] + b1v;
            if (EPI == 1) {
                v0 = fmaxf(v0, 0.f); v1 = fmaxf(v1, 0.f);
                v2 = fmaxf(v2, 0.f); v3 = fmaxf(v3, 0.f);
            }
            if (EPI == 2) {
                const float* r0 = res + (size_t)row * N + col;
                const float* r1 = res + (size_t)(row + 8) * N + col;
                v0 += r0[0]; v1 += r0[1];
                v2 += r1[0]; v3 += r1[1];
            }
            *(float2*)(C + (size_t)row * N + col)       = make_float2(v0, v1);
            *(float2*)(C + (size_t)(row + 8) * N + col) = make_float2(v2, v3);
        }
    }
}

// ---------------- Flash attention, tf32 MMA + cp.async double buffer --------
// grid = (S/128, H, B), block = 256 (8 warps), 16 query rows per warp.
static constexpr int F_STR  = 68;
static constexpr int F_TSZ  = 64 * F_STR;       // floats per tensor per stage
static constexpr int F_STG  = 2 * F_TSZ;        // K + V per stage
static constexpr int FLASH_SMEM = 2 * F_STG * 4;  // bytes

__global__ __launch_bounds__(256, 1) void flash_mma(
    const float* __restrict__ Q,
    const float* __restrict__ Kp,
    const float* __restrict__ Vp,
    const int*   __restrict__ am,
    float* __restrict__ O)
{
    extern __shared__ float sm[];
    __shared__ float addm[2][64];

    const unsigned FULL = 0xffffffffu;
    int qb = blockIdx.x, h = blockIdx.y, b = blockIdx.z;
    int tid  = threadIdx.x;
    int lane = tid & 31;
    int warp = tid >> 5;
    int gid  = lane >> 2;
    int tig  = lane & 3;

    int row0 = qb * 128 + warp * 16;
    int r1 = row0 + gid;
    int r2 = r1 + 8;
    int wrow_max = row0 + 15;

    const float scale = 0.125f;

    // cooperative KV load mapping
    int lr = tid >> 2;
    int lc = (tid & 3) * 16;
    uint32_t smb = (uint32_t)__cvta_generic_to_shared(sm);
    uint32_t koff = (lr * F_STR + lc) * 4;
    uint32_t voff = (F_TSZ + lr * F_STR + lc) * 4;
    const float* kg = Kp + ((size_t)b * S + lr) * D + h * HD + lc;
    const float* vg = Vp + ((size_t)b * S + lr) * D + h * HD + lc;

    auto issueKV = [&](int t) {
        uint32_t s = smb + (uint32_t)((t & 1) * F_STG * 4);
        const float* kp = kg + (size_t)t * 64 * D;
        const float* vp = vg + (size_t)t * 64 * D;
        #pragma unroll
        for (int i = 0; i < 16; i += 4) {
            CP16(s + koff + i * 4, kp + i);
            CP16(s + voff + i * 4, vp + i);
        }
        CP_COMMIT();
    };

    // Q fragments, pre-scaled tf32
    uint32_t qa[8][4];
    {
        const float* q1 = Q + ((size_t)b * S + r1) * D + h * HD;
        const float* q2 = Q + ((size_t)b * S + r2) * D + h * HD;
        #pragma unroll
        for (int ka = 0; ka < 8; ka++) {
            qa[ka][0] = tf32u(q1[ka * 8 + tig]     * scale);
            qa[ka][1] = tf32u(q2[ka * 8 + tig]     * scale);
            qa[ka][2] = tf32u(q1[ka * 8 + tig + 4] * scale);
            qa[ka][3] = tf32u(q2[ka * 8 + tig + 4] * scale);
        }
    }

    float m1 = -1e30f, m2 = -1e30f, l1 = 0.f, l2 = 0.f;
    float oacc[8][4];
    #pragma unroll
    for (int i = 0; i < 8; i++)
        #pragma unroll
        for (int j = 0; j < 4; j++) oacc[i][j] = 0.f;

    int ntiles = qb * 2 + 2;
    issueKV(0);
    if (tid < 64)
        addm[0][tid] = (am[(size_t)b * S + tid] != 0) ? 0.f : -1e30f;

    for (int kv = 0; kv < ntiles; kv++) {
        CP_WAIT(0);
        __syncthreads();
        // prefetch next tile (safe: all warps done with buf (kv+1)&1 per sync)
        if (kv + 1 < ntiles) {
            issueKV(kv + 1);
            if (tid < 64)
                addm[(kv + 1) & 1][tid] =
                    (am[(size_t)b * S + (kv + 1) * 64 + tid] != 0) ? 0.f : -1e30f;
        }

        if (kv * 64 <= wrow_max) {
            const float* Ks = sm + (kv & 1) * F_STG;
            const float* Vs = Ks + F_TSZ;
            const float* amr = addm[kv & 1];

            // ---- S = Q @ K^T ----
            float sc[8][4];
            #pragma unroll
            for (int na = 0; na < 8; na++)
                #pragma unroll
                for (int j = 0; j < 4; j++) sc[na][j] = 0.f;

            #pragma unroll
            for (int ka = 0; ka < 8; ka++) {
                #pragma unroll
                for (int na = 0; na < 8; na++) {
                    uint32_t b0 = __float_as_uint(Ks[(na * 8 + gid) * F_STR + ka * 8 + tig]);
                    uint32_t b1 = __float_as_uint(Ks[(na * 8 + gid) * F_STR + ka * 8 + tig + 4]);
                    MMA_TF32(sc[na], qa[ka], b0, b1);
                }
            }

            // ---- mask + row max ----
            float mt1 = -1e30f, mt2 = -1e30f;
            #pragma unroll
            for (int na = 0; na < 8; na++) {
                int key0 = kv * 64 + na * 8 + 2 * tig;
                float a0 = amr[na * 8 + 2 * tig];
                float a1 = amr[na * 8 + 2 * tig + 1];
                sc[na][0] = (key0     <= r1) ? sc[na][0] + a0 : -1e30f;
                sc[na][1] = (key0 + 1 <= r1) ? sc[na][1] + a1 : -1e30f;
                sc[na][2] = (key0     <= r2) ? sc[na][2] + a0 : -1e30f;
                sc[na][3] = (key0 + 1 <= r2) ? sc[na][3] + a1 : -1e30f;
                mt1 = fmaxf(mt1, fmaxf(sc[na][0], sc[na][1]));
                mt2 = fmaxf(mt2, fmaxf(sc[na][2], sc[na][3]));
            }
            mt1 = fmaxf(mt1, __shfl_xor_sync(FULL, mt1, 1));
            mt1 = fmaxf(mt1, __shfl_xor_sync(FULL, mt1, 2));
            mt2 = fmaxf(mt2, __shfl_xor_sync(FULL, mt2, 1));
            mt2 = fmaxf(mt2, __shfl_xor_sync(FULL, mt2, 2));

            float mn1 = fmaxf(m1, mt1);
            float mn2 = fmaxf(m2, mt2);
            float c1 = __expf(m1 - mn1);
            float c2 = __expf(m2 - mn2);
            m1 = mn1; m2 = mn2;

            // ---- exp + P conversion (C-frag -> A-frag via quad shuffles) ----
            int basel = lane & ~3;
            int srcA  = basel + (tig >> 1);
            int srcB  = srcA + 2;
            int comp  = tig & 1;
            uint32_t pa[8][4];
            float pt1 = 0.f, pt2 = 0.f;
            #pragma unroll
            for (int na = 0; na < 8; na++) {
                float e0 = __expf(sc[na][0] - mn1);
                float e1 = __expf(sc[na][1] - mn1);
                float e2 = __expf(sc[na][2] - mn2);
                float e3 = __expf(sc[na][3] - mn2);
                pt1 += e0 + e1;
                pt2 += e2 + e3;
                float x0 = __shfl_sync(FULL, e0, srcA);
                float x1 = __shfl_sync(FULL, e1, srcA);
                float y0 = __shfl_sync(FULL, e2, srcA);
                float y1 = __shfl_sync(FULL, e3, srcA);
                float z0 = __shfl_sync(FULL, e0, srcB);
                float z1 = __shfl_sync(FULL, e1, srcB);
                float w0 = __shfl_sync(FULL, e2, srcB);
                float w1 = __shfl_sync(FULL, e3, srcB);
                pa[na][0] = __float_as_uint(comp ? x1 : x0);
                pa[na][1] = __float_as_uint(comp ? y1 : y0);
                pa[na][2] = __float_as_uint(comp ? z1 : z0);
                pa[na][3] = __float_as_uint(comp ? w1 : w0);
            }
            pt1 += __shfl_xor_sync(FULL, pt1, 1);
            pt1 += __shfl_xor_sync(FULL, pt1, 2);
            pt2 += __shfl_xor_sync(FULL, pt2, 1);
            pt2 += __shfl_xor_sync(FULL, pt2, 2);
            l1 = l1 * c1 + pt1;
            l2 = l2 * c2 + pt2;

            #pragma unroll
            for (int na = 0; na < 8; na++) {
                oacc[na][0] *= c1; oacc[na][1] *= c1;
                oacc[na][2] *= c2; oacc[na][3] *= c2;
            }

            // ---- O += P @ V ----
            #pragma unroll
            for (int ka = 0; ka < 8; ka++) {
                #pragma unroll
                for (int na = 0; na < 8; na++) {
                    uint32_t b0 = __float_as_uint(Vs[(ka * 8 + tig) * F_STR + na * 8 + gid]);
                    uint32_t b1 = __float_as_uint(Vs[(ka * 8 + tig + 4) * F_STR + na * 8 + gid]);
                    MMA_TF32(oacc[na], pa[ka], b0, b1);
                }
            }
        }
        __syncthreads();
    }

    float inv1 = 1.0f / l1;
    float inv2 = 1.0f / l2;
    float* o1 = O + ((size_t)b * S + r1) * D + h * HD;
    float* o2 = O + ((size_t)b * S + r2) * D + h * HD;
    #pragma unroll
    for (int na = 0; na < 8; na++) {
        int col = na * 8 + 2 * tig;
        *(float2*)(o1 + col) = make_float2(oacc[na][0] * inv1, oacc[na][1] * inv1);
        *(float2*)(o2 + col) = make_float2(oacc[na][2] * inv2, oacc[na][3] * inv2);
    }
}

// ---------------- launch ----------------------------------------------------
extern "C" void kernel_launch(void* const* d_in, const int* in_sizes, int n_in,
                              void* d_out, int out_size)
{
    const float* x    = (const float*)d_in[0];
    const int*   am   = (const int*)  d_in[1];
    const float* ln1g = (const float*)d_in[2];
    const float* ln1b = (const float*)d_in[3];
    const float* ln2g = (const float*)d_in[4];
    const float* ln2b = (const float*)d_in[5];
    const float* Wq   = (const float*)d_in[6];
    const float* bq   = (const float*)d_in[7];
    const float* Wk   = (const float*)d_in[8];
    const float* bk   = (const float*)d_in[9];
    const float* Wv   = (const float*)d_in[10];
    const float* bv   = (const float*)d_in[11];
    const float* Wo   = (const float*)d_in[12];
    const float* bo   = (const float*)d_in[13];
    const float* W1   = (const float*)d_in[14];
    const float* b1   = (const float*)d_in[15];
    const float* W2   = (const float*)d_in[16];
    const float* b2   = (const float*)d_in[17];
    float* out = (float*)d_out;

    float *h, *q, *k, *v, *ctx, *x1, *h2, *ff;
    cudaGetSymbolAddress((void**)&h,   g_h);
    cudaGetSymbolAddress((void**)&q,   g_q);
    cudaGetSymbolAddress((void**)&k,   g_k);
    cudaGetSymbolAddress((void**)&v,   g_v);
    cudaGetSymbolAddress((void**)&ctx, g_ctx);
    cudaGetSymbolAddress((void**)&x1,  g_x1);
    cudaGetSymbolAddress((void**)&h2,  g_h2);
    cudaGetSymbolAddress((void**)&ff,  g_ff);

    static bool attr_done = false;
    if (!attr_done) {
        cudaFuncSetAttribute(mma_gemm<0>,
            cudaFuncAttributeMaxDynamicSharedMemorySize, GEMM_SMEM);
        cudaFuncSetAttribute(mma_gemm<1>,
            cudaFuncAttributeMaxDynamicSharedMemorySize, GEMM_SMEM);
        cudaFuncSetAttribute(mma_gemm<2>,
            cudaFuncAttributeMaxDynamicSharedMemorySize, GEMM_SMEM);
        cudaFuncSetAttribute(flash_mma,
            cudaFuncAttributeMaxDynamicSharedMemorySize, FLASH_SMEM);
        attr_done = true;
    }

    dim3 blk(256);
    dim3 gD(D / 128, NTOK / 128);
    dim3 gF(DFF / 128, NTOK / 128);

    ln_kernel<<<NTOK, blk>>>(x, ln1g, ln1b, h);
    mma_gemm<0><<<gD, blk, GEMM_SMEM>>>(NTOK, D, D, h, Wq, bq, nullptr, q);
    mma_gemm<0><<<gD, blk, GEMM_SMEM>>>(NTOK, D, D, h, Wk, bk, nullptr, k);
    mma_gemm<0><<<gD, blk, GEMM_SMEM>>>(NTOK, D, D, h, Wv, bv, nullptr, v);
    flash_mma<<<dim3(S / 128, H, B), blk, FLASH_SMEM>>>(q, k, v, am, ctx);
    mma_gemm<2><<<gD, blk, GEMM_SMEM>>>(NTOK, D, D, ctx, Wo, bo, x, x1);
    ln_kernel<<<NTOK, blk>>>(x1, ln2g, ln2b, h2);
    mma_gemm<1><<<gF, blk, GEMM_SMEM>>>(NTOK, DFF, D, h2, W1, b1, nullptr, ff);
    mma_gemm<2><<<gD, blk, GEMM_SMEM>>>(NTOK, D, DFF, ff, W2, b2, x1, out);
}